// round 7
// baseline (speedup 1.0000x reference)
#include <cuda_runtime.h>
#include <cuda_bf16.h>

// out[a,b] = (softmax(X[b] @ X[a]^T) * mask[a,b]) @ X[b]
// X: (384,32,32) fp32; mask/out: (384,384,32,32) fp32.
//
// mma.sync (HMMA fallback) path; tcgen05 unreachable (compute_103 PTX).
// R7: register-pressure cut (launch_bounds(128,7), split mask prefetch)
// to raise occupancy 6 -> 7 CTAs/SM; structure otherwise identical to R6.

#define NN 384
#define RS   80          // smem row stride (bytes)
#define BLKB (32 * RS)   // one 32-row array: 2560 B

typedef unsigned int u32;

// [hi 64B | lo 64B] per row, 384*32 rows = 1.5 MB (L2-resident scratch)
__device__ uint4 Xsplit[384 * 32 * 8];

static __device__ __forceinline__ u32 smem_u32(const void* p) {
    u32 a;
    asm("{ .reg .u64 t; cvta.to.shared.u64 t, %1; cvt.u32.u64 %0, t; }" : "=r"(a) : "l"(p));
    return a;
}

#define LDM4(r, addr)                                                                   \
    asm volatile("ldmatrix.sync.aligned.m8n8.x4.shared.b16 {%0,%1,%2,%3}, [%4];"        \
                 : "=r"((r)[0]), "=r"((r)[1]), "=r"((r)[2]), "=r"((r)[3]) : "r"(addr))

#define LDM4T(r, addr)                                                                  \
    asm volatile("ldmatrix.sync.aligned.m8n8.x4.trans.shared.b16 {%0,%1,%2,%3}, [%4];"  \
                 : "=r"((r)[0]), "=r"((r)[1]), "=r"((r)[2]), "=r"((r)[3]) : "r"(addr))

#define MMA(c, a, b0, b1)                                                               \
    asm volatile("mma.sync.aligned.m16n8k16.row.col.f32.bf16.bf16.f32 "                 \
                 "{%0,%1,%2,%3}, {%4,%5,%6,%7}, {%8,%9}, {%0,%1,%2,%3};"                \
                 : "+f"((c)[0]), "+f"((c)[1]), "+f"((c)[2]), "+f"((c)[3])               \
                 : "r"((a)[0]), "r"((a)[1]), "r"((a)[2]), "r"((a)[3]), "r"(b0), "r"(b1))

static __device__ __forceinline__ u32 pk_bf16(float lo, float hi) {
    u32 r;  // low half <- 'lo' (even element)
    asm("cvt.rn.bf16x2.f32 %0, %1, %2;" : "=r"(r) : "f"(hi), "f"(lo));
    return r;
}
static __device__ __forceinline__ float bf16_rt(float x) {
    return __bfloat162float(__float2bfloat16(x));
}

// exp via deg-5 2^f poly; FMA pipe only.
static __device__ __forceinline__ float fexp(float x) {
    x = fmaxf(x, -87.0f);
    const float z = x * 1.4426950408889634f;
    const int   i = __float2int_rn(z);
    const float f = z - __int2float_rn(i);
    float p = 0.0013333558f;
    p = fmaf(p, f, 0.0096181291f);
    p = fmaf(p, f, 0.0555041087f);
    p = fmaf(p, f, 0.2402265070f);
    p = fmaf(p, f, 0.6931471806f);
    p = fmaf(p, f, 1.0f);
    return p * __int_as_float((i + 127) << 23);
}

// ---- prep: split all X rows into bf16 hi/lo once ----
__global__ __launch_bounds__(128)
void prep_kernel(const float* __restrict__ x1) {
    const int idx = blockIdx.x * 128 + threadIdx.x;   // row 0..12287
    const float4* src = (const float4*)(x1 + (size_t)idx * 32);
    float v[32];
    #pragma unroll
    for (int j = 0; j < 8; j++) {
        const float4 q = src[j];
        v[4 * j] = q.x; v[4 * j + 1] = q.y; v[4 * j + 2] = q.z; v[4 * j + 3] = q.w;
    }
    uint4* dst = Xsplit + (size_t)idx * 8;
    #pragma unroll
    for (int c = 0; c < 4; c++) {
        const float* g = v + 8 * c;
        uint4 hv, lv;
        hv.x = pk_bf16(g[0], g[1]); hv.y = pk_bf16(g[2], g[3]);
        hv.z = pk_bf16(g[4], g[5]); hv.w = pk_bf16(g[6], g[7]);
        float r[8];
        #pragma unroll
        for (int i = 0; i < 8; i++) r[i] = g[i] - bf16_rt(g[i]);
        lv.x = pk_bf16(r[0], r[1]); lv.y = pk_bf16(r[2], r[3]);
        lv.z = pk_bf16(r[4], r[5]); lv.w = pk_bf16(r[6], r[7]);
        dst[c] = hv;
        dst[4 + c] = lv;
    }
}

__global__ __launch_bounds__(128, 7)
void attn_mma_kernel(const float* __restrict__ mask,
                     float* __restrict__ out) {
    // arrays: [0..3] Xb{0,1} hi/lo, [4..7] Xa{0,1} hi/lo
    __shared__ __align__(16) char sm[8 * BLKB];   // 20480 B

    const int t = threadIdx.x;
    const int w = t >> 5;
    const int l = t & 31;
    const int bx = blockIdx.x, by = blockIdx.y;

    // ---- staging: thread t -> (block w, row l); plain 128B row copy ----
    {
        const int blk  = w;                // 0,1 = b-blocks; 2,3 = a-blocks
        const int gblk = (blk < 2) ? (2 * bx + blk) : (2 * by + (blk - 2));
        const uint4* g = Xsplit + ((size_t)gblk * 32 + l) * 8;
        char* H = sm + (2 * blk) * BLKB + l * RS;
        char* L = H + BLKB;
        const int rot = l >> 3;
        #pragma unroll
        for (int c = 0; c < 4; c++) {
            const int cc = (c + rot) & 3;
            *(uint4*)(H + cc * 16) = g[cc];
            *(uint4*)(L + cc * 16) = g[4 + cc];
        }
    }
    __syncthreads();

    // ---- per-warp pair ----
    const int ai = w >> 1, bi = w & 1;
    const int a = 2 * by + ai, b = 2 * bx + bi;
    const size_t blkoff = ((size_t)a * NN + b) * 1024;

    const u32 sb = smem_u32(sm);
    const u32 XbH = sb + (2 * bi) * BLKB,      XbL = XbH + BLKB;
    const u32 XaH = sb + (4 + 2 * ai) * BLKB,  XaL = XaH + BLKB;

    // ldmatrix per-lane offsets
    const u32 aoff = (((l >> 3) & 1) * 8 + (l & 7)) * RS + ((l >> 4) & 1) * 16;
    const u32 boff = ((l >> 4) * 8 + (l & 7)) * RS + ((l >> 3) & 1) * 16;
    const u32 toff = (l & 15) * RS + ((l >> 4) & 1) * 16;   // for .trans B loads

    const float* mbase = mask + blkoff + (size_t)(l >> 2) * 32 + 2 * (l & 3);

    // mask prefetch, FIRST HALF only (rows 0..15): 16 regs instead of 32
    float2 m2[4][4];
    #pragma unroll
    for (int r4 = 0; r4 < 2; r4++) {
        const float* mrow = mbase + (size_t)(8 * r4) * 32;
        #pragma unroll
        for (int j = 0; j < 4; j++) m2[r4][j] = *(const float2*)(mrow + 8 * j);
    }

    // ---- QK: 3-term bf16 split ----
    float c[2][4][4];
    #pragma unroll
    for (int mt = 0; mt < 2; mt++)
        #pragma unroll
        for (int j = 0; j < 4; j++)
            c[mt][j][0] = c[mt][j][1] = c[mt][j][2] = c[mt][j][3] = 0.f;

    #pragma unroll
    for (int kt = 0; kt < 2; kt++) {
        u32 AH[2][4], AL[2][4], BH[2][4], BL[2][4];
        LDM4(AH[0], XbH + kt * 32 + aoff);
        LDM4(AH[1], XbH + 1280 + kt * 32 + aoff);
        LDM4(AL[0], XbL + kt * 32 + aoff);
        LDM4(AL[1], XbL + 1280 + kt * 32 + aoff);
        LDM4(BH[0], XaH + kt * 32 + boff);
        LDM4(BH[1], XaH + 1280 + kt * 32 + boff);
        LDM4(BL[0], XaL + kt * 32 + boff);
        LDM4(BL[1], XaL + 1280 + kt * 32 + boff);
        #pragma unroll
        for (int mt = 0; mt < 2; mt++)
            #pragma unroll
            for (int j = 0; j < 4; j++) {
                const int jp = j >> 1, s = (j & 1) * 2;
                MMA(c[mt][j], AH[mt], BH[jp][s], BH[jp][s + 1]);
                MMA(c[mt][j], AL[mt], BH[jp][s], BH[jp][s + 1]);
                MMA(c[mt][j], AH[mt], BL[jp][s], BL[jp][s + 1]);
            }
    }

    // mask prefetch, SECOND HALF (rows 16..31): consumed after ~2 softmax
    // groups (~300 cyc), so latency stays covered while halving the live range.
    #pragma unroll
    for (int r4 = 2; r4 < 4; r4++) {
        const float* mrow = mbase + (size_t)(8 * r4) * 32;
        #pragma unroll
        for (int j = 0; j < 4; j++) m2[r4][j] = *(const float2*)(mrow + 8 * j);
    }

    // ---- softmax (no max-sub; |qk| small) + dropout ----
    #pragma unroll
    for (int mt = 0; mt < 2; mt++)
        #pragma unroll
        for (int h = 0; h < 2; h++) {
            float s = 0.f;
            #pragma unroll
            for (int j = 0; j < 4; j++)
                #pragma unroll
                for (int i = 0; i < 2; i++) {
                    const float e = fexp(c[mt][j][2 * h + i]);
                    c[mt][j][2 * h + i] = e;
                    s += e;
                }
            s += __shfl_xor_sync(0xffffffffu, s, 1);
            s += __shfl_xor_sync(0xffffffffu, s, 2);
            const float inv = __fdividef(1.0f, s);
            const float* mf = (const float*)&m2[2 * mt + h][0];
            #pragma unroll
            for (int j = 0; j < 4; j++)
                #pragma unroll
                for (int i = 0; i < 2; i++)
                    c[mt][j][2 * h + i] *= inv * mf[2 * j + i];
        }

    // ---- AV: O = P @ Xb; B via ldmatrix.trans on row-major Xb ----
    float o[2][4][4];
    #pragma unroll
    for (int mt = 0; mt < 2; mt++)
        #pragma unroll
        for (int j = 0; j < 4; j++)
            o[mt][j][0] = o[mt][j][1] = o[mt][j][2] = o[mt][j][3] = 0.f;

    #pragma unroll
    for (int kt = 0; kt < 2; kt++) {
        u32 PH[2][4], PL[2][4];
        #pragma unroll
        for (int mt = 0; mt < 2; mt++) {
            const float* d0 = c[mt][2 * kt];
            const float* d1 = c[mt][2 * kt + 1];
            PH[mt][0] = pk_bf16(d0[0], d0[1]);
            PH[mt][1] = pk_bf16(d0[2], d0[3]);
            PH[mt][2] = pk_bf16(d1[0], d1[1]);
            PH[mt][3] = pk_bf16(d1[2], d1[3]);
            PL[mt][0] = pk_bf16(d0[0] - bf16_rt(d0[0]), d0[1] - bf16_rt(d0[1]));
            PL[mt][1] = pk_bf16(d0[2] - bf16_rt(d0[2]), d0[3] - bf16_rt(d0[3]));
            PL[mt][2] = pk_bf16(d1[0] - bf16_rt(d1[0]), d1[1] - bf16_rt(d1[1]));
            PL[mt][3] = pk_bf16(d1[2] - bf16_rt(d1[2]), d1[3] - bf16_rt(d1[3]));
        }
        // B tiles: transpose of Xb[rows (l&15)+16kt][colb] via .trans x4
        u32 BH[2][4], BL[2][4];
        LDM4T(BH[0], XbH + kt * 1280 + toff);        // out-cols j 0..15
        LDM4T(BH[1], XbH + kt * 1280 + 32 + toff);   // out-cols j 16..31
        LDM4T(BL[0], XbL + kt * 1280 + toff);
        LDM4T(BL[1], XbL + kt * 1280 + 32 + toff);
        #pragma unroll
        for (int mt = 0; mt < 2; mt++)
            #pragma unroll
            for (int j = 0; j < 4; j++) {
                const int jp = j >> 1, s = (j & 1) * 2;
                MMA(o[mt][j], PH[mt], BH[jp][s], BH[jp][s + 1]);
                MMA(o[mt][j], PL[mt], BH[jp][s], BH[jp][s + 1]);
                MMA(o[mt][j], PH[mt], BL[jp][s], BL[jp][s + 1]);
            }
    }

    // ---- output: fragment-layout STG.64 ----
    #pragma unroll
    for (int mt = 0; mt < 2; mt++)
        #pragma unroll
        for (int h = 0; h < 2; h++) {
            float* orow = out + blkoff + (size_t)(16 * mt + 8 * h + (l >> 2)) * 32 + 2 * (l & 3);
            #pragma unroll
            for (int j = 0; j < 4; j++)
                *(float2*)(orow + 8 * j) = make_float2(o[mt][j][2 * h], o[mt][j][2 * h + 1]);
        }
}

extern "C" void kernel_launch(void* const* d_in, const int* in_sizes, int n_in,
                              void* d_out, int out_size) {
    const float* x1   = (const float*)d_in[0];   // (1,384,32,32)
    const float* mask = (const float*)d_in[1];   // (384,384,32,32)
    float* out = (float*)d_out;                  // (384,384,32,32)
    (void)in_sizes; (void)n_in; (void)out_size;

    prep_kernel<<<96, 128>>>(x1);                       // 12288 rows
    dim3 grid(NN / 2, NN / 2, 1);                       // 4 pairs per CTA
    attn_mma_kernel<<<grid, 128>>>(mask, out);
}